// round 2
// baseline (speedup 1.0000x reference)
#include <cuda_runtime.h>
#include <cuda_bf16.h>
#include <cstdint>

// AdditiveModel: out[b,v] = b3[v] + sum_j dot( sigmoid( W2[g] @ sigmoid( W1m[g] @ x[b,g,:] + b1[g] ) + b2[g] ), W3[v, j*16:..] )
// with g = v*16 + j, W1m = W1 * (causal != 0) folded at smem-load time.
//
// Grid: 2048 CTAs of 256 threads. blockIdx & 15 = v (so one CTA holds exactly
// one v's weights in smem, 34 KB). blockIdx >> 4 = batch block of 256.
// Each thread owns one (b, v) output; warp lanes are consecutive batches so
// every shared-memory weight read is a warp-uniform broadcast.

#define NV   16
#define LL   16
#define HH   16
#define GG   256
#define BB   32768

__device__ __forceinline__ float fast_sigmoid(float x) {
    // sigmoid(x) = 0.5 * tanh(0.5 x) + 0.5 ; MUFU.TANH, max rel err ~2^-11
    float t;
    asm("tanh.approx.f32 %0, %1;" : "=f"(t) : "f"(0.5f * x));
    return fmaf(0.5f, t, 0.5f);
}

__device__ __forceinline__ float dot4(float4 a, float4 b, float acc) {
    acc = fmaf(a.x, b.x, acc);
    acc = fmaf(a.y, b.y, acc);
    acc = fmaf(a.z, b.z, acc);
    acc = fmaf(a.w, b.w, acc);
    return acc;
}

__global__ __launch_bounds__(256, 3)
void additive_model_kernel(const float* __restrict__ x,
                           const int*   __restrict__ causal,
                           const float* __restrict__ W1,
                           const float* __restrict__ b1,
                           const float* __restrict__ W2,
                           const float* __restrict__ b2,
                           const float* __restrict__ W3,
                           const float* __restrict__ b3,
                           float* __restrict__ out)
{
    __shared__ float sW1[16 * 256];   // [j][h][l], mask folded in
    __shared__ float sW2[16 * 256];   // [j][k][h]
    __shared__ float sB1[256];        // [j][h]
    __shared__ float sB2[256];        // [j][k]
    __shared__ float sW3[256];        // [j][k]

    const int v    = blockIdx.x & 15;
    const int bblk = blockIdx.x >> 4;
    const int tid  = threadIdx.x;

    // ---- stage weights for this v (g = v*16 + j covers W1/W2 rows v*4096 .. v*4096+4095)
    const int wbase = v * 4096;
    #pragma unroll
    for (int e = tid; e < 4096; e += 256) {
        const int l = e & 15;
        const int j = e >> 8;
        const float m = (causal[v * 256 + j * 16 + l] != 0) ? 1.0f : 0.0f;
        sW1[e] = W1[wbase + e] * m;
        sW2[e] = W2[wbase + e];
    }
    if (tid < 256) {
        sB1[tid] = b1[v * 256 + tid];
        sB2[tid] = b2[v * 256 + tid];
        sW3[tid] = W3[v * 256 + tid];
    }
    __syncthreads();

    const int   b  = bblk * 256 + tid;
    const float* xb = x + (long)b * (GG * LL) + v * 256;   // x[b, g=v*16, 0]

    float s = 0.0f;

    #pragma unroll 1
    for (int j = 0; j < 16; ++j) {
        // load x[b, v*16+j, 0:16] — 64B contiguous, 64B-aligned
        const float4* xp = reinterpret_cast<const float4*>(xb + j * 16);
        const float4 x0 = xp[0], x1 = xp[1], x2 = xp[2], x3 = xp[3];

        const float* w1 = sW1 + j * 256;
        const float* bb1 = sB1 + j * 16;

        float h1[16];
        #pragma unroll
        for (int h = 0; h < 16; ++h) {
            const float4* wr = reinterpret_cast<const float4*>(w1 + h * 16);
            float acc = bb1[h];
            acc = dot4(x0, wr[0], acc);
            acc = dot4(x1, wr[1], acc);
            acc = dot4(x2, wr[2], acc);
            acc = dot4(x3, wr[3], acc);
            h1[h] = fast_sigmoid(acc);
        }

        const float4 h0 = make_float4(h1[0],  h1[1],  h1[2],  h1[3]);
        const float4 hA = make_float4(h1[4],  h1[5],  h1[6],  h1[7]);
        const float4 hB = make_float4(h1[8],  h1[9],  h1[10], h1[11]);
        const float4 hC = make_float4(h1[12], h1[13], h1[14], h1[15]);

        const float* w2 = sW2 + j * 256;
        const float* bb2 = sB2 + j * 16;
        const float* w3 = sW3 + j * 16;

        #pragma unroll
        for (int k = 0; k < 16; ++k) {
            const float4* wr = reinterpret_cast<const float4*>(w2 + k * 16);
            float acc = bb2[k];
            acc = dot4(h0, wr[0], acc);
            acc = dot4(hA, wr[1], acc);
            acc = dot4(hB, wr[2], acc);
            acc = dot4(hC, wr[3], acc);
            s = fmaf(fast_sigmoid(acc), w3[k], s);
        }
    }

    out[b * NV + v] = s + b3[v];
}

extern "C" void kernel_launch(void* const* d_in, const int* in_sizes, int n_in,
                              void* d_out, int out_size)
{
    const float* x      = (const float*)d_in[0];
    const int*   causal = (const int*)  d_in[1];
    const float* W1     = (const float*)d_in[2];
    const float* b1     = (const float*)d_in[3];
    const float* W2     = (const float*)d_in[4];
    const float* b2     = (const float*)d_in[5];
    const float* W3     = (const float*)d_in[6];
    const float* b3     = (const float*)d_in[7];
    float* out = (float*)d_out;

    // 2048 CTAs: (B/256) batch blocks * 16 variables
    dim3 grid((BB / 256) * NV);
    additive_model_kernel<<<grid, 256>>>(x, causal, W1, b1, W2, b2, W3, b3, out);
}

// round 3
// speedup vs baseline: 1.2021x; 1.2021x over previous
#include <cuda_runtime.h>
#include <cstdint>

// AdditiveModel on GB300 — packed f32x2 FMA + smem-staged x + M=2 batch blocking.
//
// Math refactor (all folded into smem-staged weights):
//   sigmoid(z) = 0.5*tanh(0.5 z) + 0.5
//   conv1: a1 = 0.5*(W1m x + b1)            -> sW1p = 0.5*mask*W1, sB1p = 0.5*b1
//          t1 = tanh(a1); h1 = 0.5 t1 + 0.5  (h1 never materialized)
//   conv2: a2 = 0.5*(W2 h1 + b2) = (0.25 W2) t1 + (0.25*rowsum(W2) + 0.5 b2)
//          t2 = tanh(a2)
//   out   = sum 0.5*w3*t2 + (b3 + 0.5*sum w3)
//
// f32x2 pairing is across channel pairs (2hp, 2hp+1); weights live in smem as
// pre-built 64-bit pairs so the only per-use cost is one mov.b64 dup of the
// shared scalar input.

#define NV 16
#define BB 32768
typedef unsigned long long ull;

__device__ __forceinline__ ull dup2(float x) {
    ull r; asm("mov.b64 %0, {%1, %1};" : "=l"(r) : "f"(x)); return r;
}
__device__ __forceinline__ ull pack2(float lo, float hi) {
    ull r; asm("mov.b64 %0, {%1, %2};" : "=l"(r) : "f"(lo), "f"(hi)); return r;
}
__device__ __forceinline__ void unpack2(ull v, float& lo, float& hi) {
    asm("mov.b64 {%0, %1}, %2;" : "=f"(lo), "=f"(hi) : "l"(v));
}
__device__ __forceinline__ void fma2(ull& d, ull a, ull b) {
    asm("fma.rn.f32x2 %0, %1, %2, %0;" : "+l"(d) : "l"(a), "l"(b));
}
__device__ __forceinline__ float tanh_fast(float x) {
    float t; asm("tanh.approx.f32 %0, %1;" : "=f"(t) : "f"(x)); return t;
}

// dynamic smem layout (floats):
//   sX[2][512*18]          73728 B   (x tiles, 72B padded rows, double buffered)
//   sW1p[16*16*8] ull      16384 B   ([j][l][hp] pairs, 0.5*mask folded)
//   sW2p[16*16*8] ull      16384 B   ([j][h][kp] pairs, 0.25 folded)
//   sB1p[16*8]    ull       1024 B
//   sB2p[16*8]    ull       1024 B   (0.25*rowsum(W2) + 0.5*b2)
//   sW3p[16*8]    ull       1024 B   (0.5*w3 pairs)
//   sOutC                     16 B
#define SMEM_BYTES (73728 + 16384 + 16384 + 1024 + 1024 + 1024 + 16)

__global__ __launch_bounds__(256, 2)
void additive_model_kernel(const float* __restrict__ x,
                           const int*   __restrict__ causal,
                           const float* __restrict__ W1,
                           const float* __restrict__ b1,
                           const float* __restrict__ W2,
                           const float* __restrict__ b2,
                           const float* __restrict__ W3,
                           const float* __restrict__ b3,
                           float* __restrict__ out)
{
    extern __shared__ float smem[];
    float* sX0   = smem;                         // 512*18
    float* sX1   = smem + 512 * 18;
    ull*   sW1p  = (ull*)(smem + 2 * 512 * 18);  // 2048
    ull*   sW2p  = sW1p + 2048;                  // 2048
    ull*   sB1p  = sW2p + 2048;                  // 128
    ull*   sB2p  = sB1p + 128;                   // 128
    ull*   sW3p  = sB2p + 128;                   // 128
    float* sOutC = (float*)(sW3p + 128);

    const int v    = blockIdx.x & 15;
    const int bblk = blockIdx.x >> 4;
    const int tid  = threadIdx.x;
    const int g0   = v * 16;

    // ---- stage weights (pre-paired, scales folded) ----
    #pragma unroll
    for (int i = 0; i < 8; ++i) {
        const int e  = tid + i * 256;          // 0..2047
        const int j  = e >> 7;
        const int m2 = (e >> 3) & 15;          // l for W1, h for W2
        const int p  = e & 7;                  // hp / kp
        const int g  = g0 + j;
        // W1 pair (mask depends on (g, l) only)
        const float ms = (causal[g * 16 + m2] != 0) ? 0.5f : 0.0f;
        sW1p[e] = pack2(ms * W1[(g * 16 + 2 * p) * 16 + m2],
                        ms * W1[(g * 16 + 2 * p + 1) * 16 + m2]);
        // W2 pair: sW2p[(j*16+h)*8+kp] = 0.25*(W2[g][2kp][h], W2[g][2kp+1][h])
        sW2p[e] = pack2(0.25f * W2[g * 256 + (2 * p) * 16 + m2],
                        0.25f * W2[g * 256 + (2 * p + 1) * 16 + m2]);
    }
    if (tid < 128) {
        const int j = tid >> 3, p = tid & 7;
        const int g = g0 + j;
        sB1p[tid] = pack2(0.5f * b1[g * 16 + 2 * p], 0.5f * b1[g * 16 + 2 * p + 1]);
        float s0 = 0.f, s1 = 0.f;
        #pragma unroll
        for (int h = 0; h < 16; ++h) {
            s0 += W2[g * 256 + (2 * p) * 16 + h];
            s1 += W2[g * 256 + (2 * p + 1) * 16 + h];
        }
        sB2p[tid] = pack2(0.25f * s0 + 0.5f * b2[g * 16 + 2 * p],
                          0.25f * s1 + 0.5f * b2[g * 16 + 2 * p + 1]);
        sW3p[tid] = pack2(0.5f * W3[v * 256 + j * 16 + 2 * p],
                          0.5f * W3[v * 256 + j * 16 + 2 * p + 1]);
    }
    if (tid == 0) {
        float c = b3[v];
        #pragma unroll 1
        for (int m = 0; m < 256; ++m) c += 0.5f * W3[v * 256 + m];
        *sOutC = c;
    }

    // ---- x staging (coalesced cp.async into padded smem tile) ----
    const float* xg = x + (size_t)bblk * 512 * 4096 + g0 * 16;  // batch row 0, g=g0, l=0

    // tile j = 0 into sX0
    {
        #pragma unroll
        for (int i = 0; i < 16; ++i) {
            const int idx = tid + i * 256;   // 0..4095
            const int r = idx >> 3, u = idx & 7;
            const float* src = xg + (size_t)r * 4096 + u * 2;
            uint32_t dst = (uint32_t)__cvta_generic_to_shared(sX0 + r * 18 + u * 2);
            asm volatile("cp.async.ca.shared.global [%0], [%1], 8;" :: "r"(dst), "l"(src));
        }
        asm volatile("cp.async.commit_group;");
    }

    ull sp0 = 0ull, sp1 = 0ull;   // paired out accumulators across j

    #pragma unroll 1
    for (int j = 0; j < 16; ++j) {
        asm volatile("cp.async.wait_group 0;" ::: "memory");
        __syncthreads();

        if (j < 15) {   // stage tile j+1 into the other buffer
            float* dbuf = ((j + 1) & 1) ? sX1 : sX0;
            #pragma unroll
            for (int i = 0; i < 16; ++i) {
                const int idx = tid + i * 256;
                const int r = idx >> 3, u = idx & 7;
                const float* src = xg + (size_t)r * 4096 + (j + 1) * 16 + u * 2;
                uint32_t dst = (uint32_t)__cvta_generic_to_shared(dbuf + r * 18 + u * 2);
                asm volatile("cp.async.ca.shared.global [%0], [%1], 8;" :: "r"(dst), "l"(src));
            }
            asm volatile("cp.async.commit_group;");
        }

        const float* xbuf = (j & 1) ? sX1 : sX0;
        const float* xr0 = xbuf + tid * 18;
        const float* xr1 = xbuf + (tid + 256) * 18;

        // ---- conv1: a = 0.5*(W1m x + b1), paired over h ----
        ull a0[8], a1[8];
        #pragma unroll
        for (int hp = 0; hp < 8; ++hp) { a0[hp] = sB1p[j * 8 + hp]; a1[hp] = a0[hp]; }

        const ulonglong2* w1 = (const ulonglong2*)(sW1p + j * 128);
        #pragma unroll
        for (int l2 = 0; l2 < 8; ++l2) {
            const float2 xa = *(const float2*)(xr0 + l2 * 2);
            const float2 xb = *(const float2*)(xr1 + l2 * 2);
            ulonglong2 p0 = w1[l2 * 8 + 0], p1 = w1[l2 * 8 + 1],
                       p2 = w1[l2 * 8 + 2], p3 = w1[l2 * 8 + 3];
            ull d0 = dup2(xa.x), d1 = dup2(xb.x);
            fma2(a0[0], p0.x, d0); fma2(a1[0], p0.x, d1);
            fma2(a0[1], p0.y, d0); fma2(a1[1], p0.y, d1);
            fma2(a0[2], p1.x, d0); fma2(a1[2], p1.x, d1);
            fma2(a0[3], p1.y, d0); fma2(a1[3], p1.y, d1);
            fma2(a0[4], p2.x, d0); fma2(a1[4], p2.x, d1);
            fma2(a0[5], p2.y, d0); fma2(a1[5], p2.y, d1);
            fma2(a0[6], p3.x, d0); fma2(a1[6], p3.x, d1);
            fma2(a0[7], p3.y, d0); fma2(a1[7], p3.y, d1);
            p0 = w1[l2 * 8 + 4]; p1 = w1[l2 * 8 + 5];
            p2 = w1[l2 * 8 + 6]; p3 = w1[l2 * 8 + 7];
            d0 = dup2(xa.y); d1 = dup2(xb.y);
            fma2(a0[0], p0.x, d0); fma2(a1[0], p0.x, d1);
            fma2(a0[1], p0.y, d0); fma2(a1[1], p0.y, d1);
            fma2(a0[2], p1.x, d0); fma2(a1[2], p1.x, d1);
            fma2(a0[3], p1.y, d0); fma2(a1[3], p1.y, d1);
            fma2(a0[4], p2.x, d0); fma2(a1[4], p2.x, d1);
            fma2(a0[5], p2.y, d0); fma2(a1[5], p2.y, d1);
            fma2(a0[6], p3.x, d0); fma2(a1[6], p3.x, d1);
            fma2(a0[7], p3.y, d0); fma2(a1[7], p3.y, d1);
        }

        float t0[16], t1[16];
        #pragma unroll
        for (int hp = 0; hp < 8; ++hp) {
            float lo, hi;
            unpack2(a0[hp], lo, hi);
            t0[2 * hp] = tanh_fast(lo); t0[2 * hp + 1] = tanh_fast(hi);
            unpack2(a1[hp], lo, hi);
            t1[2 * hp] = tanh_fast(lo); t1[2 * hp + 1] = tanh_fast(hi);
        }

        // ---- conv2: c = (0.25 W2) t + c0, paired over k ----
        ull c0[8], c1[8];
        #pragma unroll
        for (int kp = 0; kp < 8; ++kp) { c0[kp] = sB2p[j * 8 + kp]; c1[kp] = c0[kp]; }

        const ulonglong2* w2 = (const ulonglong2*)(sW2p + j * 128);
        #pragma unroll
        for (int h = 0; h < 16; ++h) {
            const ulonglong2 q0 = w2[h * 4 + 0], q1 = w2[h * 4 + 1],
                             q2 = w2[h * 4 + 2], q3 = w2[h * 4 + 3];
            const ull d0 = dup2(t0[h]), d1 = dup2(t1[h]);
            fma2(c0[0], q0.x, d0); fma2(c1[0], q0.x, d1);
            fma2(c0[1], q0.y, d0); fma2(c1[1], q0.y, d1);
            fma2(c0[2], q1.x, d0); fma2(c1[2], q1.x, d1);
            fma2(c0[3], q1.y, d0); fma2(c1[3], q1.y, d1);
            fma2(c0[4], q2.x, d0); fma2(c1[4], q2.x, d1);
            fma2(c0[5], q2.y, d0); fma2(c1[5], q2.y, d1);
            fma2(c0[6], q3.x, d0); fma2(c1[6], q3.x, d1);
            fma2(c0[7], q3.y, d0); fma2(c1[7], q3.y, d1);
        }

        // ---- epilogue: sp += (0.5 w3) * tanh(c), paired ----
        #pragma unroll
        for (int kp = 0; kp < 8; ++kp) {
            const ull w3 = sW3p[j * 8 + kp];
            float lo, hi;
            unpack2(c0[kp], lo, hi);
            fma2(sp0, w3, pack2(tanh_fast(lo), tanh_fast(hi)));
            unpack2(c1[kp], lo, hi);
            fma2(sp1, w3, pack2(tanh_fast(lo), tanh_fast(hi)));
        }
    }

    const float outC = *sOutC;
    float lo, hi;
    unpack2(sp0, lo, hi);
    out[(size_t)(bblk * 512 + tid) * NV + v] = lo + hi + outC;
    unpack2(sp1, lo, hi);
    out[(size_t)(bblk * 512 + tid + 256) * NV + v] = lo + hi + outC;
}

extern "C" void kernel_launch(void* const* d_in, const int* in_sizes, int n_in,
                              void* d_out, int out_size)
{
    const float* x      = (const float*)d_in[0];
    const int*   causal = (const int*)  d_in[1];
    const float* W1     = (const float*)d_in[2];
    const float* b1     = (const float*)d_in[3];
    const float* W2     = (const float*)d_in[4];
    const float* b2     = (const float*)d_in[5];
    const float* W3     = (const float*)d_in[6];
    const float* b3     = (const float*)d_in[7];
    float* out = (float*)d_out;

    static int configured = 0;
    if (!configured) {
        cudaFuncSetAttribute(additive_model_kernel,
                             cudaFuncAttributeMaxDynamicSharedMemorySize, SMEM_BYTES);
        configured = 1;
    }

    dim3 grid((BB / 512) * NV);   // 64 batch blocks * 16 variables = 1024 CTAs
    additive_model_kernel<<<grid, 256, SMEM_BYTES>>>(x, causal, W1, b1, W2, b2, W3, b3, out);
}

// round 5
// speedup vs baseline: 1.3252x; 1.1024x over previous
#include <cuda_runtime.h>
#include <cstdint>

// AdditiveModel on GB300 — packed f32x2 FMA + warp-private cp.async x pipelines.
//
// Math (folded into smem-staged weights):
//   sigmoid(z) = 0.5*tanh(0.5 z) + 0.5
//   conv1: a1 = 0.5*(W1m x + b1); t1 = tanh(a1)       (h1 = 0.5 t1 + 0.5, never materialized)
//   conv2: a2 = (0.25 W2) t1 + (0.25*rowsum(W2) + 0.5 b2); t2 = tanh(a2)
//   out   = sum 0.5*w3*t2 + (b3 + 0.5*sum w3)
//
// Each warp owns 64 batches (M=2 per thread) and its own double-buffered x tile
// in smem, staged with its own cp.async groups -> NO __syncthreads in the j loop,
// warps free-run and de-phase (fma vs MUFU bursts interleave across warps).

#define NV 16
#define BB 32768
typedef unsigned long long ull;

__device__ __forceinline__ ull dup2(float x) {
    ull r; asm("mov.b64 %0, {%1, %1};" : "=l"(r) : "f"(x)); return r;
}
__device__ __forceinline__ ull pack2(float lo, float hi) {
    ull r; asm("mov.b64 %0, {%1, %2};" : "=l"(r) : "f"(lo), "f"(hi)); return r;
}
__device__ __forceinline__ void unpack2(ull v, float& lo, float& hi) {
    asm("mov.b64 {%0, %1}, %2;" : "=f"(lo), "=f"(hi) : "l"(v));
}
__device__ __forceinline__ void fma2(ull& d, ull a, ull b) {
    asm("fma.rn.f32x2 %0, %1, %2, %0;" : "+l"(d) : "l"(a), "l"(b));
}
__device__ __forceinline__ float tanh_fast(float x) {
    float t; asm("tanh.approx.f32 %0, %1;" : "=f"(t) : "f"(x)); return t;
}

// dynamic smem (floats):
//   sX[8 warps][2 buf][64 rows][18]   73728 B  (72B padded rows)
//   sW1p[2048] ull  16384 B   ([j][l][hp] pairs, 0.5*mask folded)
//   sW2p[2048] ull  16384 B   ([j][h][kp] pairs, 0.25 folded)
//   sB1p[128]  ull   1024 B
//   sB2p[128]  ull   1024 B
//   sW3p[128]  ull   1024 B
//   sOutC                16 B
#define SMEM_BYTES (73728 + 16384 + 16384 + 1024 + 1024 + 1024 + 16)

__global__ __launch_bounds__(256, 2)
void additive_model_kernel(const float* __restrict__ x,
                           const int*   __restrict__ causal,
                           const float* __restrict__ W1,
                           const float* __restrict__ b1,
                           const float* __restrict__ W2,
                           const float* __restrict__ b2,
                           const float* __restrict__ W3,
                           const float* __restrict__ b3,
                           float* __restrict__ out)
{
    extern __shared__ float smem[];
    float* sXall = smem;                         // 8 * 2 * 64 * 18
    ull*   sW1p  = (ull*)(smem + 18432);         // 2048
    ull*   sW2p  = sW1p + 2048;
    ull*   sB1p  = sW2p + 2048;
    ull*   sB2p  = sB1p + 128;
    ull*   sW3p  = sB2p + 128;
    float* sOutC = (float*)(sW3p + 128);

    const int v    = blockIdx.x & 15;
    const int bblk = blockIdx.x >> 4;
    const int tid  = threadIdx.x;
    const int wid  = tid >> 5;
    const int lane = tid & 31;
    const int g0   = v * 16;

    // ---- stage weights (pre-paired, scales folded) ----
    #pragma unroll
    for (int i = 0; i < 8; ++i) {
        const int e  = tid + i * 256;          // 0..2047
        const int j  = e >> 7;
        const int m2 = (e >> 3) & 15;          // l for W1, h for W2
        const int p  = e & 7;                  // hp / kp
        const int g  = g0 + j;
        const float ms = (causal[g * 16 + m2] != 0) ? 0.5f : 0.0f;
        sW1p[e] = pack2(ms * W1[(g * 16 + 2 * p) * 16 + m2],
                        ms * W1[(g * 16 + 2 * p + 1) * 16 + m2]);
        sW2p[e] = pack2(0.25f * W2[g * 256 + (2 * p) * 16 + m2],
                        0.25f * W2[g * 256 + (2 * p + 1) * 16 + m2]);
    }
    if (tid < 128) {
        const int j = tid >> 3, p = tid & 7;
        const int g = g0 + j;
        sB1p[tid] = pack2(0.5f * b1[g * 16 + 2 * p], 0.5f * b1[g * 16 + 2 * p + 1]);
        float s0 = 0.f, s1 = 0.f;
        #pragma unroll
        for (int h = 0; h < 16; ++h) {
            s0 += W2[g * 256 + (2 * p) * 16 + h];
            s1 += W2[g * 256 + (2 * p + 1) * 16 + h];
        }
        sB2p[tid] = pack2(0.25f * s0 + 0.5f * b2[g * 16 + 2 * p],
                          0.25f * s1 + 0.5f * b2[g * 16 + 2 * p + 1]);
        sW3p[tid] = pack2(0.5f * W3[v * 256 + j * 16 + 2 * p],
                          0.5f * W3[v * 256 + j * 16 + 2 * p + 1]);
    }
    if (tid == 0) {
        float c = b3[v];
        #pragma unroll 1
        for (int m = 0; m < 256; ++m) c += 0.5f * W3[v * 256 + m];
        *sOutC = c;
    }
    __syncthreads();   // only barrier in the kernel

    // ---- warp-private x staging state ----
    // warp owns batches bblk*512 + wid*64 + [0..63]
    const float* xw = x + (size_t)(bblk * 512 + wid * 64) * 4096 + g0 * 16;
    float* xbuf0 = sXall + wid * (2 * 64 * 18);        // buffer 0
    float* xbuf1 = xbuf0 + 64 * 18;                    // buffer 1

    const int srow   = lane >> 3;      // 0..3
    const int schunk = (lane & 7) * 2; // float offset 0,2,..14
    const float* xsrc = xw + (size_t)srow * 4096 + schunk;
    const uint32_t d0 = (uint32_t)__cvta_generic_to_shared(xbuf0 + srow * 18 + schunk);
    const uint32_t d1 = (uint32_t)__cvta_generic_to_shared(xbuf1 + srow * 18 + schunk);

    // prologue: stage tile j=0 into buffer 0
    #pragma unroll
    for (int k = 0; k < 16; ++k) {
        asm volatile("cp.async.ca.shared.global [%0], [%1], 8;"
                     :: "r"(d0 + k * (4 * 18 * 4)), "l"(xsrc + (size_t)k * 4 * 4096));
    }
    asm volatile("cp.async.commit_group;");

    const float* xr0b = xbuf0 + lane * 18;             // this thread's rows
    const float* xr1b = xbuf0 + (lane + 32) * 18;
    const int bufStride = 64 * 18;

    ull sp0 = 0ull, sp1 = 0ull;

    #pragma unroll 1
    for (int j = 0; j < 16; ++j) {
        // prefetch tile j+1 into the other buffer, then wait for tile j
        if (j < 15) {
            const uint32_t dn = ((j + 1) & 1) ? d1 : d0;
            const float* sn = xsrc + (size_t)(j + 1) * 16;
            #pragma unroll
            for (int k = 0; k < 16; ++k) {
                asm volatile("cp.async.ca.shared.global [%0], [%1], 8;"
                             :: "r"(dn + k * (4 * 18 * 4)), "l"(sn + (size_t)k * 4 * 4096));
            }
            asm volatile("cp.async.commit_group;");
            asm volatile("cp.async.wait_group 1;" ::: "memory");
        } else {
            asm volatile("cp.async.wait_group 0;" ::: "memory");
        }
        __syncwarp();

        const int boff = (j & 1) * bufStride;
        const float* xr0 = xr0b + boff;
        const float* xr1 = xr1b + boff;

        // ---- conv1: a = 0.5*(W1m x + b1), paired over h ----
        ull a0[8], a1[8];
        #pragma unroll
        for (int hp = 0; hp < 8; ++hp) { a0[hp] = sB1p[j * 8 + hp]; a1[hp] = a0[hp]; }

        const ulonglong2* w1 = (const ulonglong2*)(sW1p + j * 128);
        #pragma unroll
        for (int l2 = 0; l2 < 8; ++l2) {
            const float2 xa = *(const float2*)(xr0 + l2 * 2);
            const float2 xb = *(const float2*)(xr1 + l2 * 2);
            ulonglong2 p0 = w1[l2 * 8 + 0], p1 = w1[l2 * 8 + 1],
                       p2 = w1[l2 * 8 + 2], p3 = w1[l2 * 8 + 3];
            ull da = dup2(xa.x), db = dup2(xb.x);
            fma2(a0[0], p0.x, da); fma2(a1[0], p0.x, db);
            fma2(a0[1], p0.y, da); fma2(a1[1], p0.y, db);
            fma2(a0[2], p1.x, da); fma2(a1[2], p1.x, db);
            fma2(a0[3], p1.y, da); fma2(a1[3], p1.y, db);
            fma2(a0[4], p2.x, da); fma2(a1[4], p2.x, db);
            fma2(a0[5], p2.y, da); fma2(a1[5], p2.y, db);
            fma2(a0[6], p3.x, da); fma2(a1[6], p3.x, db);
            fma2(a0[7], p3.y, da); fma2(a1[7], p3.y, db);
            p0 = w1[l2 * 8 + 4]; p1 = w1[l2 * 8 + 5];
            p2 = w1[l2 * 8 + 6]; p3 = w1[l2 * 8 + 7];
            da = dup2(xa.y); db = dup2(xb.y);
            fma2(a0[0], p0.x, da); fma2(a1[0], p0.x, db);
            fma2(a0[1], p0.y, da); fma2(a1[1], p0.y, db);
            fma2(a0[2], p1.x, da); fma2(a1[2], p1.x, db);
            fma2(a0[3], p1.y, da); fma2(a1[3], p1.y, db);
            fma2(a0[4], p2.x, da); fma2(a1[4], p2.x, db);
            fma2(a0[5], p2.y, da); fma2(a1[5], p2.y, db);
            fma2(a0[6], p3.x, da); fma2(a1[6], p3.x, db);
            fma2(a0[7], p3.y, da); fma2(a1[7], p3.y, db);
        }

        float t0[16], t1[16];
        #pragma unroll
        for (int hp = 0; hp < 8; ++hp) {
            float lo, hi;
            unpack2(a0[hp], lo, hi);
            t0[2 * hp] = tanh_fast(lo); t0[2 * hp + 1] = tanh_fast(hi);
            unpack2(a1[hp], lo, hi);
            t1[2 * hp] = tanh_fast(lo); t1[2 * hp + 1] = tanh_fast(hi);
        }

        // ---- conv2: c = (0.25 W2) t + c0, paired over k ----
        ull c0[8], c1[8];
        #pragma unroll
        for (int kp = 0; kp < 8; ++kp) { c0[kp] = sB2p[j * 8 + kp]; c1[kp] = c0[kp]; }

        const ulonglong2* w2 = (const ulonglong2*)(sW2p + j * 128);
        #pragma unroll
        for (int h = 0; h < 16; ++h) {
            const ulonglong2 q0 = w2[h * 4 + 0], q1 = w2[h * 4 + 1],
                             q2 = w2[h * 4 + 2], q3 = w2[h * 4 + 3];
            const ull da = dup2(t0[h]), db = dup2(t1[h]);
            fma2(c0[0], q0.x, da); fma2(c1[0], q0.x, db);
            fma2(c0[1], q0.y, da); fma2(c1[1], q0.y, db);
            fma2(c0[2], q1.x, da); fma2(c1[2], q1.x, db);
            fma2(c0[3], q1.y, da); fma2(c1[3], q1.y, db);
            fma2(c0[4], q2.x, da); fma2(c1[4], q2.x, db);
            fma2(c0[5], q2.y, da); fma2(c1[5], q2.y, db);
            fma2(c0[6], q3.x, da); fma2(c1[6], q3.x, db);
            fma2(c0[7], q3.y, da); fma2(c1[7], q3.y, db);
        }

        // ---- epilogue: sp += (0.5 w3) * tanh(c), paired ----
        #pragma unroll
        for (int kp = 0; kp < 8; ++kp) {
            const ull w3 = sW3p[j * 8 + kp];
            float lo, hi;
            unpack2(c0[kp], lo, hi);
            fma2(sp0, w3, pack2(tanh_fast(lo), tanh_fast(hi)));
            unpack2(c1[kp], lo, hi);
            fma2(sp1, w3, pack2(tanh_fast(lo), tanh_fast(hi)));
        }
    }

    const float outC = *sOutC;
    const int b0 = bblk * 512 + wid * 64 + lane;
    float lo, hi;
    unpack2(sp0, lo, hi);
    out[(size_t)b0 * NV + v] = lo + hi + outC;
    unpack2(sp1, lo, hi);
    out[(size_t)(b0 + 32) * NV + v] = lo + hi + outC;
}

extern "C" void kernel_launch(void* const* d_in, const int* in_sizes, int n_in,
                              void* d_out, int out_size)
{
    const float* x      = (const float*)d_in[0];
    const int*   causal = (const int*)  d_in[1];
    const float* W1     = (const float*)d_in[2];
    const float* b1     = (const float*)d_in[3];
    const float* W2     = (const float*)d_in[4];
    const float* b2     = (const float*)d_in[5];
    const float* W3     = (const float*)d_in[6];
    const float* b3     = (const float*)d_in[7];
    float* out = (float*)d_out;

    static int configured = 0;
    if (!configured) {
        cudaFuncSetAttribute(additive_model_kernel,
                             cudaFuncAttributeMaxDynamicSharedMemorySize, SMEM_BYTES);
        configured = 1;
    }

    dim3 grid((BB / 512) * NV);   // 64 batch blocks * 16 variables = 1024 CTAs
    additive_model_kernel<<<grid, 256, SMEM_BYTES>>>(x, causal, W1, b1, W2, b2, W3, b3, out);
}